// round 1
// baseline (speedup 1.0000x reference)
#include <cuda_runtime.h>
#include <cstdint>

// Problem constants (fixed by setup_inputs)
#define BATCH 4
#define CIN   128
#define COUT  256
#define EDGES 20000
#define NCOL  (BATCH * EDGES)        // 80000
#define K0    (CIN * 5)              // 640
#define K1    (COUT * 5)             // 1280

// Scratch (device globals: allocation inside kernel_launch is forbidden)
__device__ float g_y[(size_t)COUT * NCOL];       // conv0 output / residual (82 MB)
__device__ float g_wt0[K0 * COUT];               // W0^T  [k][o]
__device__ float g_wt1[K1 * COUT];               // W1^T  [k][o]
__device__ float g_scale[COUT];
__device__ float g_shift[COUT];

// ---------------------------------------------------------------------------
// Transpose weights: w[o][c][s] (row-major) -> Wt[k=c*5+s][o]
// ---------------------------------------------------------------------------
__global__ void transpose_w_kernel(const float* __restrict__ w0,
                                   const float* __restrict__ w1) {
    int i = blockIdx.x * blockDim.x + threadIdx.x;
    if (i < K0 * COUT) {
        int o = i / K0, k = i - o * K0;
        g_wt0[k * COUT + o] = w0[i];
    }
    if (i < K1 * COUT) {
        int o = i / K1, k = i - o * K1;
        g_wt1[k * COUT + o] = w1[i];
    }
}

// ---------------------------------------------------------------------------
// BN stats over relu(y): per-channel mean/var over (B,E) = 80000 values.
// Emits scale = gamma * rsqrt(var+eps), shift = beta - mean*scale.
// ---------------------------------------------------------------------------
__global__ void bn_stats_kernel(const float* __restrict__ gamma,
                                const float* __restrict__ beta) {
    const int c = blockIdx.x;
    const int tid = threadIdx.x;
    const float4* row = reinterpret_cast<const float4*>(g_y + (size_t)c * NCOL);
    float s = 0.f, ss = 0.f;
    for (int i = tid; i < NCOL / 4; i += 256) {
        float4 v = row[i];
        float a = fmaxf(v.x, 0.f), b = fmaxf(v.y, 0.f);
        float d = fmaxf(v.z, 0.f), e = fmaxf(v.w, 0.f);
        s  += (a + b) + (d + e);
        ss += (a * a + b * b) + (d * d + e * e);
    }
    __shared__ float sh_s[256], sh_ss[256];
    sh_s[tid] = s; sh_ss[tid] = ss;
    __syncthreads();
    #pragma unroll
    for (int o = 128; o > 0; o >>= 1) {
        if (tid < o) { sh_s[tid] += sh_s[tid + o]; sh_ss[tid] += sh_ss[tid + o]; }
        __syncthreads();
    }
    if (tid == 0) {
        const float inv = 1.0f / (float)NCOL;
        float mean = sh_s[0] * inv;
        float var  = sh_ss[0] * inv - mean * mean;
        float sc   = gamma[c] * rsqrtf(var + 1e-5f);
        g_scale[c] = sc;
        g_shift[c] = beta[c] - mean * sc;
    }
}

// ---------------------------------------------------------------------------
// Fused mesh-conv GEMM.
//   C[256, 80000] = Wt^T @ G,  G[k=c*5+s][n] built on the fly by gather.
// Block: BM=256 (all of M), BN=64, BK=20 (4 channels x 5 features).
// 256 threads; warp w owns cols w*8..w*8+7 (smem broadcast), lane l owns
// rows l, l+32, ..., l+224 (conflict-free scalar LDS). 8x8 accum per thread.
// MODE 0: src = x [B,CIN,E], writes g_y.
// MODE 1: src = bn(relu(g_y)) applied on the fly, epilogue adds residual g_y,
//         relu, writes out [B,COUT,E] via smem staging for coalescing.
// ---------------------------------------------------------------------------
template <int MODE>
__global__ __launch_bounds__(256, 2)
void mesh_gemm_kernel(const float* __restrict__ x,
                      const int*   __restrict__ gidx,
                      float*       __restrict__ outp) {
    constexpr int K      = (MODE == 0) ? K0 : K1;
    constexpr int STRIDE = (MODE == 0) ? EDGES : NCOL;

    __shared__ float As[20 * 256];
    __shared__ float Bs[20 * 64];
    __shared__ int   cbs[5 * 64];
    __shared__ float ssc[256], ssh[256];
    __shared__ float Cs[32 * 65];   // MODE1 epilogue staging

    const int tid = threadIdx.x;
    const int n0  = blockIdx.x * 64;

    // Per-column gather bases (constant over the whole K loop)
    if (tid < 64) {
        const int n = n0 + tid;
        const int b = n / EDGES;
        const int e = n - b * EDGES;
        const int4 gi = *reinterpret_cast<const int4*>(gidx + 4 * n);
        if (MODE == 0) {
            const int bb = b * (CIN * EDGES);
            cbs[        tid] = bb + e;
            cbs[ 64   + tid] = bb + gi.x;
            cbs[128   + tid] = bb + gi.y;
            cbs[192   + tid] = bb + gi.z;
            cbs[256   + tid] = bb + gi.w;
        } else {
            const int bb = b * EDGES;
            cbs[        tid] = n;
            cbs[ 64   + tid] = bb + gi.x;
            cbs[128   + tid] = bb + gi.y;
            cbs[192   + tid] = bb + gi.z;
            cbs[256   + tid] = bb + gi.w;
        }
    }
    if (MODE == 1) { ssc[tid] = g_scale[tid]; ssh[tid] = g_shift[tid]; }
    __syncthreads();

    const int c_local = tid >> 6;       // 0..3 : channel within K-tile
    const int col     = tid & 63;       // 0..63: column within block
    const int p0 = cbs[col], p1 = cbs[64 + col], p2 = cbs[128 + col],
              p3 = cbs[192 + col], p4 = cbs[256 + col];

    const int lane = tid & 31;
    const int wrp  = tid >> 5;

    const float* __restrict__ Wt  = (MODE == 0) ? g_wt0 : g_wt1;
    const float* __restrict__ src = (MODE == 0) ? x : g_y;

    float acc[8][8];
    #pragma unroll
    for (int i = 0; i < 8; i++)
        #pragma unroll
        for (int j = 0; j < 8; j++) acc[i][j] = 0.f;

    // Software-pipelined global loads: prefetch tile (W + gathers) into regs.
    float4 regW[5];
    float  rg[5];

    {   // prefetch k0 = 0
        const float4* wt4 = reinterpret_cast<const float4*>(Wt);
        #pragma unroll
        for (int i = 0; i < 5; i++) regW[i] = __ldg(wt4 + tid * 5 + i);
        const int c = c_local;
        const float* sp = src + (size_t)c * STRIDE;
        rg[0] = __ldg(sp + p0); rg[1] = __ldg(sp + p1); rg[2] = __ldg(sp + p2);
        rg[3] = __ldg(sp + p3); rg[4] = __ldg(sp + p4);
    }

    #pragma unroll 1
    for (int k0 = 0; k0 < K; k0 += 20) {
        __syncthreads();   // previous tile's compute done

        // ---- store prefetched tile into smem ----
        #pragma unroll
        for (int i = 0; i < 5; i++)
            reinterpret_cast<float4*>(As)[tid * 5 + i] = regW[i];
        {
            float g0 = rg[0], g1 = rg[1], g2 = rg[2], g3 = rg[3], g4 = rg[4];
            if (MODE == 1) {
                const int c = (k0 / 5) + c_local;
                const float scl = ssc[c], sht = ssh[c];
                g0 = fmaxf(g0, 0.f) * scl + sht;
                g1 = fmaxf(g1, 0.f) * scl + sht;
                g2 = fmaxf(g2, 0.f) * scl + sht;
                g3 = fmaxf(g3, 0.f) * scl + sht;
                g4 = fmaxf(g4, 0.f) * scl + sht;
            }
            float* bp = Bs + (c_local * 5) * 64 + col;
            bp[0]   = g0;
            bp[64]  = g1 + g2 * 0.f + g3;   // placeholder removed below
            bp[64]  = g1 + g3;
            bp[128] = g2 + g4;
            bp[192] = fabsf(g1 - g3);
            bp[256] = fabsf(g2 - g4);
        }
        __syncthreads();   // tile ready

        // ---- prefetch next tile (latency hides under compute) ----
        if (k0 + 20 < K) {
            const float4* wt4 =
                reinterpret_cast<const float4*>(Wt + (size_t)(k0 + 20) * 256);
            #pragma unroll
            for (int i = 0; i < 5; i++) regW[i] = __ldg(wt4 + tid * 5 + i);
            const int c = ((k0 + 20) / 5) + c_local;
            const float* sp = src + (size_t)c * STRIDE;
            rg[0] = __ldg(sp + p0); rg[1] = __ldg(sp + p1);
            rg[2] = __ldg(sp + p2); rg[3] = __ldg(sp + p3);
            rg[4] = __ldg(sp + p4);
        }

        // ---- compute 20 K-steps ----
        #pragma unroll
        for (int kk = 0; kk < 20; kk++) {
            const float4 blo = *reinterpret_cast<const float4*>(&Bs[kk * 64 + wrp * 8]);
            const float4 bhi = *reinterpret_cast<const float4*>(&Bs[kk * 64 + wrp * 8 + 4]);
            const float bv[8] = {blo.x, blo.y, blo.z, blo.w,
                                 bhi.x, bhi.y, bhi.z, bhi.w};
            float av[8];
            #pragma unroll
            for (int i = 0; i < 8; i++) av[i] = As[kk * 256 + lane + 32 * i];
            #pragma unroll
            for (int i = 0; i < 8; i++)
                #pragma unroll
                for (int j = 0; j < 8; j++)
                    acc[i][j] = fmaf(av[i], bv[j], acc[i][j]);
        }
    }

    // ---- epilogue ----
    if (MODE == 0) {
        #pragma unroll
        for (int i = 0; i < 8; i++) {
            const int row = lane + 32 * i;
            float* dst = g_y + (size_t)row * NCOL + n0 + wrp * 8;
            float4 v0 = make_float4(acc[i][0], acc[i][1], acc[i][2], acc[i][3]);
            float4 v1 = make_float4(acc[i][4], acc[i][5], acc[i][6], acc[i][7]);
            *reinterpret_cast<float4*>(dst)     = v0;
            *reinterpret_cast<float4*>(dst + 4) = v1;
        }
    } else {
        // residual + relu, staged through smem for coalesced [B,COUT,E] stores
        #pragma unroll 1
        for (int i = 0; i < 8; i++) {
            __syncthreads();
            {
                const int row = lane + 32 * i;
                const float* yrow = g_y + (size_t)row * NCOL + n0 + wrp * 8;
                const float4 y0 = *reinterpret_cast<const float4*>(yrow);
                const float4 y1 = *reinterpret_cast<const float4*>(yrow + 4);
                float r[8];
                r[0] = fmaxf(acc[i][0] + y0.x, 0.f);
                r[1] = fmaxf(acc[i][1] + y0.y, 0.f);
                r[2] = fmaxf(acc[i][2] + y0.z, 0.f);
                r[3] = fmaxf(acc[i][3] + y0.w, 0.f);
                r[4] = fmaxf(acc[i][4] + y1.x, 0.f);
                r[5] = fmaxf(acc[i][5] + y1.y, 0.f);
                r[6] = fmaxf(acc[i][6] + y1.z, 0.f);
                r[7] = fmaxf(acc[i][7] + y1.w, 0.f);
                #pragma unroll
                for (int j = 0; j < 8; j++)
                    Cs[lane * 65 + wrp * 8 + j] = r[j];
            }
            __syncthreads();
            // rows covered this pass: lane + 32*i for all lanes == 32 rows
            const int row_l = tid >> 3;          // 0..31 (local row in Cs)
            const int j0    = (tid & 7) * 8;     // column chunk
            const int row   = row_l + 32 * i;    // global output channel
            #pragma unroll
            for (int j = 0; j < 8; j++) {
                const int n = n0 + j0 + j;
                const int b = n / EDGES;
                const int e = n - b * EDGES;
                outp[((size_t)(b * COUT + row)) * EDGES + e] = Cs[row_l * 65 + j0 + j];
            }
        }
    }
}

// ---------------------------------------------------------------------------
extern "C" void kernel_launch(void* const* d_in, const int* in_sizes, int n_in,
                              void* d_out, int out_size) {
    const float* x     = (const float*)d_in[0];
    const int*   gidx  = (const int*)  d_in[1];
    const float* w0    = (const float*)d_in[2];
    const float* w1    = (const float*)d_in[3];
    const float* gamma = (const float*)d_in[4];
    const float* beta  = (const float*)d_in[5];
    float* outp = (float*)d_out;

    transpose_w_kernel<<<(K1 * COUT + 255) / 256, 256>>>(w0, w1);
    mesh_gemm_kernel<0><<<NCOL / 64, 256>>>(x, gidx, nullptr);
    bn_stats_kernel<<<COUT, 256>>>(gamma, beta);
    mesh_gemm_kernel<1><<<NCOL / 64, 256>>>(x, gidx, outp);
}

// round 4
// speedup vs baseline: 1.7888x; 1.7888x over previous
#include <cuda_runtime.h>
#include <cuda_bf16.h>
#include <cstdint>

// ---------------------------------------------------------------------------
// Problem constants
// ---------------------------------------------------------------------------
#define BATCH  4
#define CIN    128
#define COUT   256
#define EDGES  20000
#define NCOL   80000           // BATCH*EDGES
#define K0     640             // CIN*5
#define K1     1280            // COUT*5
#define NT     625             // NCOL/128 N-tiles

// Shared-memory layout (bytes, dynamic)
// A: 2 stages x 2 sel(hi/lo) x [256 rows x 40 bf16] = 2*2*20480 = 81920
// B: 2 sel x [128 rows x 40 bf16] = 20480
// idx: 5*128 int = 2560 ; ssc/ssh: 256 f32 each
#define SM_A    0
#define SM_B    81920
#define SM_IDX  102400
#define SM_SSC  104960
#define SM_SSH  105984
#define SMEM_BYTES 132096      // epilogue overlay: 256*129*4

// ---------------------------------------------------------------------------
// Device scratch
// ---------------------------------------------------------------------------
__device__ float g_xt[(size_t)NCOL * CIN];     // x edge-major [n][c]
__device__ float g_yc[(size_t)COUT * NCOL];    // y channel-major [o][n]
__device__ float g_yt[(size_t)NCOL * COUT];    // y edge-major [n][o]
__device__ unsigned char g_w0p[20 * 32768];    // W0 chunks: [kc][hi/lo][256][32] bf16
__device__ unsigned char g_w1p[40 * 32768];    // W1 chunks
__device__ float g_scale[COUT];
__device__ float g_shift[COUT];

// ---------------------------------------------------------------------------
// PTX helpers (all arch-agnostic: valid on sm_100 base target)
// ---------------------------------------------------------------------------
__device__ __forceinline__ uint32_t smem_u32(const void* p) {
    uint32_t a;
    asm("{ .reg .u64 t; cvta.to.shared.u64 t, %1; cvt.u32.u64 %0, t; }"
        : "=r"(a) : "l"(p));
    return a;
}

#define CP_ASYNC16(dst, src) \
    asm volatile("cp.async.cg.shared.global [%0], [%1], 16;" \
                 :: "r"(dst), "l"(src) : "memory")
#define CP_COMMIT() asm volatile("cp.async.commit_group;" ::: "memory")
#define CP_WAIT0()  asm volatile("cp.async.wait_group 0;"  ::: "memory")

#define LDM_X4(r, addr) \
    asm volatile("ldmatrix.sync.aligned.m8n8.x4.shared.b16 {%0,%1,%2,%3}, [%4];" \
        : "=r"((r)[0]), "=r"((r)[1]), "=r"((r)[2]), "=r"((r)[3]) : "r"(addr))

#define MMA16816(d, a, b0_, b1_) \
    asm volatile("mma.sync.aligned.m16n8k16.row.col.f32.bf16.bf16.f32 " \
        "{%0,%1,%2,%3}, {%4,%5,%6,%7}, {%8,%9}, {%0,%1,%2,%3};" \
        : "+f"((d)[0]), "+f"((d)[1]), "+f"((d)[2]), "+f"((d)[3]) \
        : "r"((a)[0]), "r"((a)[1]), "r"((a)[2]), "r"((a)[3]), \
          "r"(b0_), "r"(b1_))

// ---------------------------------------------------------------------------
// Weight prep: w[o][c][s] -> per-chunk bf16 hi/lo, K permuted to k = s*C + c.
// Chunk layout: g_wp + kc*32768 + sel*16384 + o*64 + kk*2   (kk = k%32)
// ---------------------------------------------------------------------------
__global__ void prep_w_kernel(const float* __restrict__ w0,
                              const float* __restrict__ w1) {
    int idx = blockIdx.x * blockDim.x + threadIdx.x;
    if (idx < COUT * K0) {
        int o = idx / K0, r = idx - o * K0, c = r / 5, s = r - 5 * c;
        float v = w0[idx];
        int k = s * CIN + c, kc = k >> 5, kk = k & 31;
        __nv_bfloat16 h = __float2bfloat16(v);
        __nv_bfloat16 l = __float2bfloat16(v - __bfloat162float(h));
        size_t off = (size_t)kc * 32768 + (size_t)o * 64 + kk * 2;
        *(__nv_bfloat16*)(g_w0p + off) = h;
        *(__nv_bfloat16*)(g_w0p + off + 16384) = l;
    }
    if (idx < COUT * K1) {
        int o = idx / K1, r = idx - o * K1, c = r / 5, s = r - 5 * c;
        float v = w1[idx];
        int k = s * COUT + c, kc = k >> 5, kk = k & 31;
        __nv_bfloat16 h = __float2bfloat16(v);
        __nv_bfloat16 l = __float2bfloat16(v - __bfloat162float(h));
        size_t off = (size_t)kc * 32768 + (size_t)o * 64 + kk * 2;
        *(__nv_bfloat16*)(g_w1p + off) = h;
        *(__nv_bfloat16*)(g_w1p + off + 16384) = l;
    }
}

// ---------------------------------------------------------------------------
// x [B][C][E] -> g_xt [n][c]
// ---------------------------------------------------------------------------
__global__ void transpose_x_kernel(const float* __restrict__ x) {
    __shared__ float t[32][33];
    int e0 = blockIdx.x * 32, c0 = blockIdx.y * 32, b = blockIdx.z;
    int tx = threadIdx.x, ty = threadIdx.y;
    #pragma unroll
    for (int i = 0; i < 4; i++)
        t[ty + i * 8][tx] = x[((size_t)b * CIN + (c0 + ty + i * 8)) * EDGES + e0 + tx];
    __syncthreads();
    #pragma unroll
    for (int i = 0; i < 4; i++)
        g_xt[(size_t)(b * EDGES + e0 + ty + i * 8) * CIN + c0 + tx] = t[tx][ty + i * 8];
}

// ---------------------------------------------------------------------------
// BN stats over relu(y) per channel  ->  scale/shift
// ---------------------------------------------------------------------------
__global__ void bn_stats_kernel(const float* __restrict__ gamma,
                                const float* __restrict__ beta) {
    const int ch = blockIdx.x;
    const int tid = threadIdx.x;
    const float4* row = reinterpret_cast<const float4*>(g_yc + (size_t)ch * NCOL);
    float s = 0.f, ss = 0.f;
    for (int i = tid; i < NCOL / 4; i += 256) {
        float4 v = row[i];
        float a = fmaxf(v.x, 0.f), b = fmaxf(v.y, 0.f);
        float d = fmaxf(v.z, 0.f), e = fmaxf(v.w, 0.f);
        s  += (a + b) + (d + e);
        ss += (a * a + b * b) + (d * d + e * e);
    }
    __shared__ float sh_s[256], sh_ss[256];
    sh_s[tid] = s; sh_ss[tid] = ss;
    __syncthreads();
    #pragma unroll
    for (int o = 128; o > 0; o >>= 1) {
        if (tid < o) { sh_s[tid] += sh_s[tid + o]; sh_ss[tid] += sh_ss[tid + o]; }
        __syncthreads();
    }
    if (tid == 0) {
        const float inv = 1.0f / (float)NCOL;
        float mean = sh_s[0] * inv;
        float var  = sh_ss[0] * inv - mean * mean;
        float scv  = gamma[ch] * rsqrtf(var + 1e-5f);
        g_scale[ch] = scv;
        g_shift[ch] = beta[ch] - mean * scv;
    }
}

// ---------------------------------------------------------------------------
// Fused mesh-conv GEMM, mma.sync bf16 with 3-term hi/lo split.
// CTA: M=256 x N=128, 512 threads (16 warps, warp tile 32x64).
// K chunks of 32 (one symmetric feature s x 32 channels), K order k = s*C+c.
// MODE 0: src=g_xt; writes g_yc + g_yt.
// MODE 1: src=bn(relu(g_yt)) on the fly; epilogue residual+relu -> out.
// ---------------------------------------------------------------------------
template <int MODE>
__global__ __launch_bounds__(512, 1)
void gemm_kernel(float* __restrict__ outp, const int* __restrict__ gidx) {
    extern __shared__ unsigned char smem[];
    constexpr int C   = MODE ? COUT : CIN;
    constexpr int NCH = C / 32;          // channel chunks per feature
    constexpr int KCN = 5 * NCH;         // total K chunks
    const float* __restrict__ src = MODE ? g_yt : g_xt;
    const unsigned char* __restrict__ gw = MODE ? g_w1p : g_w0p;

    const uint32_t sb = smem_u32(smem);
    int*   idxs = (int*)  (smem + SM_IDX);
    float* ssc  = (float*)(smem + SM_SSC);
    float* ssh  = (float*)(smem + SM_SSH);

    const int tid = threadIdx.x;
    const int n0  = blockIdx.x * 128;

    if (tid < 128) {
        int n = n0 + tid;
        int base = (n / EDGES) * EDGES;
        int4 gi = *(const int4*)(gidx + 4 * n);
        idxs[tid]       = n;
        idxs[128 + tid] = base + gi.x;
        idxs[256 + tid] = base + gi.y;
        idxs[384 + tid] = base + gi.z;
        idxs[512 + tid] = base + gi.w;
    }
    if (MODE == 1 && tid < 256) { ssc[tid] = g_scale[tid]; ssh[tid] = g_shift[tid]; }
    __syncthreads();

    // B-build role: 4 threads per column, 8 channels each
    const int col = tid & 127;
    const int j0  = (tid >> 7) * 8;
    const int iSelf = idxs[col],      i1 = idxs[128 + col], i2 = idxs[256 + col],
              i3    = idxs[384 + col], i4 = idxs[512 + col];

    // MMA role
    const int wid = tid >> 5, lane = tid & 31;
    const int wm = wid & 7;      // M block: wm*32
    const int wn = wid >> 3;     // N block: wn*64

    float acc[2][8][4];
    #pragma unroll
    for (int a = 0; a < 2; a++)
        #pragma unroll
        for (int b = 0; b < 8; b++)
            #pragma unroll
            for (int c = 0; c < 4; c++) acc[a][b][c] = 0.f;

    // ---- helpers -----------------------------------------------------------
    auto issueA = [&](int kc, int stage) {
        const unsigned char* sp = gw + (size_t)kc * 32768 + (size_t)tid * 64;
        #pragma unroll
        for (int q = 0; q < 4; q++) {
            int gb  = tid * 64 + q * 16;
            int sel = gb >> 14;           // hi=0 / lo=1 section (16384 B each)
            int r   = gb & 16383;
            int m   = r >> 6;             // weight row (64 B per row)
            int ko  = r & 63;
            uint32_t dst = sb + stage * 40960 + sel * 20480 + m * 80 + ko;
            CP_ASYNC16(dst, sp + q * 16);
        }
        CP_COMMIT();
    };

    float4 va0, va1, vb0, vb1;
    auto prefB = [&](int kc) {
        int s = kc / NCH, c0 = (kc - s * NCH) * 32;
        int ra, rb;
        if (s == 0)              { ra = iSelf; rb = iSelf; }
        else if (s == 1 || s == 3) { ra = i1; rb = i3; }
        else                     { ra = i2; rb = i4; }
        const float* pa = src + (size_t)ra * C + c0 + j0;
        const float* pb = src + (size_t)rb * C + c0 + j0;
        va0 = __ldg((const float4*)pa);
        va1 = __ldg((const float4*)(pa + 4));
        vb0 = __ldg((const float4*)pb);
        vb1 = __ldg((const float4*)(pb + 4));
    };

    auto stsB = [&](int kc) {
        int s = kc / NCH, c0 = (kc - s * NCH) * 32;
        float fa[8] = {va0.x, va0.y, va0.z, va0.w, va1.x, va1.y, va1.z, va1.w};
        float fb[8] = {vb0.x, vb0.y, vb0.z, vb0.w, vb1.x, vb1.y, vb1.z, vb1.w};
        uint32_t* bh = (uint32_t*)(smem + SM_B + col * 80 + j0 * 2);
        uint32_t* bl = (uint32_t*)(smem + SM_B + 10240 + col * 80 + j0 * 2);
        #pragma unroll
        for (int qq = 0; qq < 4; qq++) {
            float f2[2];
            #pragma unroll
            for (int e = 0; e < 2; e++) {
                int q = qq * 2 + e;
                float A_ = fa[q], B_ = fb[q];
                if (MODE == 1) {
                    float sc = ssc[c0 + j0 + q], sh = ssh[c0 + j0 + q];
                    A_ = fmaxf(A_, 0.f) * sc + sh;
                    B_ = fmaxf(B_, 0.f) * sc + sh;
                }
                f2[e] = (s == 0) ? A_ : ((s <= 2) ? (A_ + B_) : fabsf(A_ - B_));
            }
            __nv_bfloat16 h0 = __float2bfloat16(f2[0]);
            __nv_bfloat16 h1 = __float2bfloat16(f2[1]);
            __nv_bfloat16 l0 = __float2bfloat16(f2[0] - __bfloat162float(h0));
            __nv_bfloat16 l1 = __float2bfloat16(f2[1] - __bfloat162float(h1));
            bh[qq] = (uint32_t)__bfloat16_as_ushort(h0) |
                     ((uint32_t)__bfloat16_as_ushort(h1) << 16);
            bl[qq] = (uint32_t)__bfloat16_as_ushort(l0) |
                     ((uint32_t)__bfloat16_as_ushort(l1) << 16);
        }
    };

    // ---- main loop ---------------------------------------------------------
    issueA(0, 0);
    prefB(0);

    #pragma unroll 1
    for (int kc = 0; kc < KCN; kc++) {
        const int st = kc & 1;
        CP_WAIT0();
        __syncthreads();            // A[cur] landed; Bs free (prev MMA done)
        stsB(kc);
        if (kc + 1 < KCN) issueA(kc + 1, st ^ 1);
        __syncthreads();            // Bs ready
        if (kc + 1 < KCN) prefB(kc + 1);   // gathers overlap MMA below

        const uint32_t abase = sb + st * 40960;
        #pragma unroll
        for (int ks = 0; ks < 2; ks++) {
            uint32_t Ah[2][4], Al[2][4];
            #pragma unroll
            for (int mi = 0; mi < 2; mi++) {
                uint32_t ar = abase +
                    (uint32_t)((wm * 32 + mi * 16 + (lane & 15)) * 80 +
                               (ks * 16 + ((lane >> 4) << 3)) * 2);
                LDM_X4(Ah[mi], ar);
                LDM_X4(Al[mi], ar + 20480);
            }
            #pragma unroll
            for (int ni = 0; ni < 4; ni++) {
                uint32_t br = sb + SM_B +
                    (uint32_t)((wn * 64 + ni * 16 + (lane & 7) +
                                ((lane >> 3) & 1) * 8) * 80 +
                               (ks * 16 + ((lane >> 4) << 3)) * 2);
                uint32_t Bh[4], Bl[4];
                LDM_X4(Bh, br);
                LDM_X4(Bl, br + 10240);
                #pragma unroll
                for (int mi = 0; mi < 2; mi++) {
                    MMA16816(acc[mi][ni * 2],     Ah[mi], Bh[0], Bh[2]);
                    MMA16816(acc[mi][ni * 2],     Ah[mi], Bl[0], Bl[2]);
                    MMA16816(acc[mi][ni * 2],     Al[mi], Bh[0], Bh[2]);
                    MMA16816(acc[mi][ni * 2 + 1], Ah[mi], Bh[1], Bh[3]);
                    MMA16816(acc[mi][ni * 2 + 1], Ah[mi], Bl[1], Bl[3]);
                    MMA16816(acc[mi][ni * 2 + 1], Al[mi], Bh[1], Bh[3]);
                }
            }
        }
    }

    // ---- epilogue: stage 256x128 tile in smem ------------------------------
    __syncthreads();
    float* epi = (float*)smem;      // [256][129]
    #pragma unroll
    for (int mi = 0; mi < 2; mi++)
        #pragma unroll
        for (int nj = 0; nj < 8; nj++) {
            int r = wm * 32 + mi * 16 + (lane >> 2);
            int c = wn * 64 + nj * 8 + 2 * (lane & 3);
            epi[r * 129 + c]           = acc[mi][nj][0];
            epi[r * 129 + c + 1]       = acc[mi][nj][1];
            epi[(r + 8) * 129 + c]     = acc[mi][nj][2];
            epi[(r + 8) * 129 + c + 1] = acc[mi][nj][3];
        }
    __syncthreads();

    if (MODE == 0) {
        #pragma unroll 4
        for (int i = 0; i < 64; i++) {
            int idx = tid + i * 512;
            int o = idx >> 7, n = idx & 127;
            g_yc[(size_t)o * NCOL + n0 + n] = epi[o * 129 + n];
        }
        #pragma unroll 4
        for (int i = 0; i < 64; i++) {
            int idx = tid + i * 512;
            int n = idx >> 8, o = idx & 255;
            g_yt[(size_t)(n0 + n) * COUT + o] = epi[o * 129 + n];
        }
    } else {
        #pragma unroll 4
        for (int i = 0; i < 64; i++) {
            int idx = tid + i * 512;
            int o = idx >> 7, n = idx & 127;
            float v = epi[o * 129 + n] + g_yc[(size_t)o * NCOL + n0 + n];
            v = fmaxf(v, 0.f);
            int nn = n0 + n;
            int b = nn / EDGES;
            int e = nn - b * EDGES;
            outp[((size_t)(b * COUT + o)) * EDGES + e] = v;
        }
    }
}

// ---------------------------------------------------------------------------
extern "C" void kernel_launch(void* const* d_in, const int* in_sizes, int n_in,
                              void* d_out, int out_size) {
    const float* x     = (const float*)d_in[0];
    const int*   gidx  = (const int*)  d_in[1];
    const float* w0    = (const float*)d_in[2];
    const float* w1    = (const float*)d_in[3];
    const float* gamma = (const float*)d_in[4];
    const float* beta  = (const float*)d_in[5];
    float* outp = (float*)d_out;

    cudaFuncSetAttribute(gemm_kernel<0>,
                         cudaFuncAttributeMaxDynamicSharedMemorySize, SMEM_BYTES);
    cudaFuncSetAttribute(gemm_kernel<1>,
                         cudaFuncAttributeMaxDynamicSharedMemorySize, SMEM_BYTES);

    prep_w_kernel<<<(COUT * K1 + 255) / 256, 256>>>(w0, w1);
    transpose_x_kernel<<<dim3(EDGES / 32, CIN / 32, BATCH), dim3(32, 8)>>>(x);
    gemm_kernel<0><<<NT, 512, SMEM_BYTES>>>(nullptr, gidx);
    bn_stats_kernel<<<COUT, 256>>>(gamma, beta);
    gemm_kernel<1><<<NT, 512, SMEM_BYTES>>>(outp, gidx);
}